// round 7
// baseline (speedup 1.0000x reference)
#include <cuda_runtime.h>
#include <cstdint>

// Problem constants (fixed by the dataset)
#define NN 100000
#define NE 1600000
#define F  32
#define MAXDEG 64          // P(Poisson(16) >= 64) ~ 1e-19 over 100k nodes
#define MAXDEG_SHIFT 6

// Scratch (no cudaMalloc allowed) — referenced directly from device code.
// g_cnt starts zeroed (BSS) and is restored to zero by k_aggregate each call.
__device__ int   g_cnt[NN];                        // in-degree (excl. self-loop)
__device__ int   g_ebin[(size_t)NN * MAXDEG];      // src ids, fixed-stride bins
__device__ float g_h[(size_t)NN * F];              // projected features

// ---------------------------------------------------------------------------
// Kernel 1: fused histogram + bin fill.
// r = cnt[d]++ ; ebin[d*64 + r] = src. No scan, no start gather, no relpos.
// ---------------------------------------------------------------------------
__global__ void k_histfill(const int* __restrict__ src,
                           const int* __restrict__ dst, int e) {
    int i = blockIdx.x * blockDim.x + threadIdx.x;
    if (i >= e) return;
    int d = __ldg(dst + i);
    int s = __ldg(src + i);
    int r = atomicAdd(&g_cnt[d], 1);
    if (r < MAXDEG)
        g_ebin[((size_t)d << MAXDEG_SHIFT) + r] = s;
}

// ---------------------------------------------------------------------------
// Kernel 2: h[v] = (x[v] * rsqrt(deg[v])) @ W^T, W staged in smem.
// Chunked accumulators (xr[32] + acc[8]) keep register pressure moderate.
// deg = cnt + 1 (self-loop).
// ---------------------------------------------------------------------------
__global__ void __launch_bounds__(256) k_project(
        const float* __restrict__ x,
        const float* __restrict__ W, int n) {
    __shared__ float sW[F][F];
    for (int i = threadIdx.x; i < F * F; i += blockDim.x)
        sW[i / F][i % F] = W[i];
    __syncthreads();

    int v = blockIdx.x * blockDim.x + threadIdx.x;
    if (v >= n) return;

    float s = rsqrtf((float)(g_cnt[v] + 1));

    float xr[F];
    const float4* xp = reinterpret_cast<const float4*>(x + (size_t)v * F);
#pragma unroll
    for (int i = 0; i < F / 4; i++) {
        float4 q = __ldg(xp + i);
        xr[4 * i + 0] = q.x * s;
        xr[4 * i + 1] = q.y * s;
        xr[4 * i + 2] = q.z * s;
        xr[4 * i + 3] = q.w * s;
    }

    float4* hp = reinterpret_cast<float4*>(g_h + (size_t)v * F);
#pragma unroll 1
    for (int chunk = 0; chunk < 4; chunk++) {
        float acc[8];
#pragma unroll
        for (int o = 0; o < 8; o++) acc[o] = 0.0f;
#pragma unroll
        for (int i = 0; i < F; i++) {
            float xi = xr[i];
#pragma unroll
            for (int o = 0; o < 8; o++)
                acc[o] = fmaf(xi, sW[chunk * 8 + o][i], acc[o]);
        }
        hp[chunk * 2 + 0] = make_float4(acc[0], acc[1], acc[2], acc[3]);
        hp[chunk * 2 + 1] = make_float4(acc[4], acc[5], acc[6], acc[7]);
    }
}

// ---------------------------------------------------------------------------
// Kernel 3: warp-per-node gather + fused epilogue; restores g_cnt[v] = 0 so
// the next kernel_launch call sees pristine counters (replaces k_zero).
// ---------------------------------------------------------------------------
__global__ void k_aggregate(const float* __restrict__ bias,
                            float* __restrict__ out, int n) {
    int t = blockIdx.x * blockDim.x + threadIdx.x;
    int v = t >> 5;
    int lane = t & 31;
    if (v >= n) return;

    int cnt = g_cnt[v];
    if (cnt > MAXDEG) cnt = MAXDEG;
    if (lane == 0) g_cnt[v] = 0;          // self-restore for next call

    const int* bin = g_ebin + ((size_t)v << MAXDEG_SHIFT);
    float acc = g_h[(size_t)v * F + lane];   // self-loop contribution

    int i = 0;
    for (; i + 8 <= cnt; i += 8) {
        int s0 = __ldg(bin + i + 0);
        int s1 = __ldg(bin + i + 1);
        int s2 = __ldg(bin + i + 2);
        int s3 = __ldg(bin + i + 3);
        int s4 = __ldg(bin + i + 4);
        int s5 = __ldg(bin + i + 5);
        int s6 = __ldg(bin + i + 6);
        int s7 = __ldg(bin + i + 7);
        float a0 = __ldg(g_h + (size_t)s0 * F + lane);
        float a1 = __ldg(g_h + (size_t)s1 * F + lane);
        float a2 = __ldg(g_h + (size_t)s2 * F + lane);
        float a3 = __ldg(g_h + (size_t)s3 * F + lane);
        float a4 = __ldg(g_h + (size_t)s4 * F + lane);
        float a5 = __ldg(g_h + (size_t)s5 * F + lane);
        float a6 = __ldg(g_h + (size_t)s6 * F + lane);
        float a7 = __ldg(g_h + (size_t)s7 * F + lane);
        acc += ((a0 + a1) + (a2 + a3)) + ((a4 + a5) + (a6 + a7));
    }
    for (; i + 2 <= cnt; i += 2) {
        int s0 = __ldg(bin + i + 0);
        int s1 = __ldg(bin + i + 1);
        float a0 = __ldg(g_h + (size_t)s0 * F + lane);
        float a1 = __ldg(g_h + (size_t)s1 * F + lane);
        acc += a0 + a1;
    }
    if (i < cnt) {
        int s = __ldg(bin + i);
        acc += __ldg(g_h + (size_t)s * F + lane);
    }

    float r = rsqrtf((float)(cnt + 1));
    float b = __ldg(bias + lane);
    out[(size_t)v * F + lane] = fmaxf(fmaf(acc, r, b), 0.0f);
}

// ---------------------------------------------------------------------------
// Launch
// Inputs (metadata order): feature [N*32 f32], src [E i32], dst [E i32],
//                          W [32*32 f32], bias [32 f32]
// Output: [N*32] f32
// ---------------------------------------------------------------------------
extern "C" void kernel_launch(void* const* d_in, const int* in_sizes, int n_in,
                              void* d_out, int out_size) {
    const float* feature = (const float*)d_in[0];
    const int*   src     = (const int*)d_in[1];
    const int*   dst     = (const int*)d_in[2];
    const float* W       = (const float*)d_in[3];
    const float* bias    = (const float*)d_in[4];
    float*       out     = (float*)d_out;

    int n = in_sizes[0] / F;   // 100000
    int e = in_sizes[1];       // 1600000

    const int B = 256;

    k_histfill<<<(e + B - 1) / B, B>>>(src, dst, e);
    k_project<<<(n + B - 1) / B, B>>>(feature, W, n);

    long long athreads = (long long)n * 32;
    int agg_blocks = (int)((athreads + B - 1) / B);
    k_aggregate<<<agg_blocks, B>>>(bias, out, n);
}

// round 8
// speedup vs baseline: 1.1794x; 1.1794x over previous
#include <cuda_runtime.h>
#include <cstdint>

// Problem constants (fixed by the dataset)
#define NN 100000
#define NE 1600000
#define F  32

// Scratch (no cudaMalloc allowed) — referenced directly from device code.
// g_cnt / g_total start zeroed (BSS) and are restored by k_aggregate each call.
__device__ int           g_cnt[NN];          // in-degree (excl. self-loop)
__device__ int           g_start[NN];        // packed bin start offsets
__device__ unsigned char g_relpos[NE];       // slot within dst bin (max deg << 255)
__device__ int           g_ebin[NE];         // src ids grouped by dst (packed)
__device__ int           g_total;            // global bin allocator
__device__ float         g_h[(size_t)NN * F];// projected features

// ---------------------------------------------------------------------------
// Kernel 1: histogram of dst; keep returned slot (as byte) so fill is atomic-free
// ---------------------------------------------------------------------------
__global__ void k_hist(const int* __restrict__ dst, int e) {
    int i = blockIdx.x * blockDim.x + threadIdx.x;
    if (i < e) {
        int d = __ldg(dst + i);
        g_relpos[i] = (unsigned char)atomicAdd(&g_cnt[d], 1);
    }
}

// ---------------------------------------------------------------------------
// Kernel 2 (fused): packed-bin allocation (warp scan + one global atomic per
// warp) + projection h[v] = (x[v] * rsqrt(deg[v])) @ W^T, chunked accumulators.
// ---------------------------------------------------------------------------
__global__ void __launch_bounds__(256) k_allocproject(
        const float* __restrict__ x,
        const float* __restrict__ W, int n) {
    __shared__ float sW[F][F];
    for (int i = threadIdx.x; i < F * F; i += blockDim.x)
        sW[i / F][i % F] = W[i];
    __syncthreads();

    int t = blockIdx.x * blockDim.x + threadIdx.x;
    int lane = t & 31;
    int v = t;

    // ---- bin allocation: inclusive warp scan of counts ----
    int c = (v < n) ? g_cnt[v] : 0;
    int inc = c;
#pragma unroll
    for (int off = 1; off < 32; off <<= 1) {
        int tmp = __shfl_up_sync(0xFFFFFFFFu, inc, off);
        if (lane >= off) inc += tmp;
    }
    int excl = inc - c;
    int base = 0;
    if (lane == 31) base = atomicAdd(&g_total, inc);
    base = __shfl_sync(0xFFFFFFFFu, base, 31);
    if (v < n) g_start[v] = base + excl;

    // ---- projection ----
    if (v >= n) return;

    float s = rsqrtf((float)(c + 1));

    float xr[F];
    const float4* xp = reinterpret_cast<const float4*>(x + (size_t)v * F);
#pragma unroll
    for (int i = 0; i < F / 4; i++) {
        float4 q = __ldg(xp + i);
        xr[4 * i + 0] = q.x * s;
        xr[4 * i + 1] = q.y * s;
        xr[4 * i + 2] = q.z * s;
        xr[4 * i + 3] = q.w * s;
    }

    float4* hp = reinterpret_cast<float4*>(g_h + (size_t)v * F);
#pragma unroll 1
    for (int chunk = 0; chunk < 4; chunk++) {
        float acc[8];
#pragma unroll
        for (int o = 0; o < 8; o++) acc[o] = 0.0f;
#pragma unroll
        for (int i = 0; i < F; i++) {
            float xi = xr[i];
#pragma unroll
            for (int o = 0; o < 8; o++)
                acc[o] = fmaf(xi, sW[chunk * 8 + o][i], acc[o]);
        }
        hp[chunk * 2 + 0] = make_float4(acc[0], acc[1], acc[2], acc[3]);
        hp[chunk * 2 + 1] = make_float4(acc[4], acc[5], acc[6], acc[7]);
    }
}

// ---------------------------------------------------------------------------
// Kernel 3: fill packed bins — pure streaming, slot precomputed by k_hist
// ---------------------------------------------------------------------------
__global__ void k_fill(const int* __restrict__ src,
                       const int* __restrict__ dst, int e) {
    int i = blockIdx.x * blockDim.x + threadIdx.x;
    if (i >= e) return;
    int d = __ldg(dst + i);
    g_ebin[g_start[d] + (int)g_relpos[i]] = __ldg(src + i);
}

// ---------------------------------------------------------------------------
// Kernel 4: warp-per-node gather + fused epilogue; self-restores counters so
// the next kernel_launch call starts clean (replaces k_zero).
// ---------------------------------------------------------------------------
__global__ void k_aggregate(const float* __restrict__ bias,
                            float* __restrict__ out, int n) {
    int t = blockIdx.x * blockDim.x + threadIdx.x;
    int v = t >> 5;
    int lane = t & 31;
    if (v >= n) return;

    int start = g_start[v];
    int cnt = g_cnt[v];
    int end = start + cnt;
    if (lane == 0) g_cnt[v] = 0;          // self-restore counters
    if (t == 0) g_total = 0;              // self-restore allocator

    float acc = g_h[(size_t)v * F + lane];   // self-loop contribution

    int i = start;
    for (; i + 8 <= end; i += 8) {
        int s0 = __ldcs(g_ebin + i + 0);
        int s1 = __ldcs(g_ebin + i + 1);
        int s2 = __ldcs(g_ebin + i + 2);
        int s3 = __ldcs(g_ebin + i + 3);
        int s4 = __ldcs(g_ebin + i + 4);
        int s5 = __ldcs(g_ebin + i + 5);
        int s6 = __ldcs(g_ebin + i + 6);
        int s7 = __ldcs(g_ebin + i + 7);
        float a0 = __ldg(g_h + (size_t)s0 * F + lane);
        float a1 = __ldg(g_h + (size_t)s1 * F + lane);
        float a2 = __ldg(g_h + (size_t)s2 * F + lane);
        float a3 = __ldg(g_h + (size_t)s3 * F + lane);
        float a4 = __ldg(g_h + (size_t)s4 * F + lane);
        float a5 = __ldg(g_h + (size_t)s5 * F + lane);
        float a6 = __ldg(g_h + (size_t)s6 * F + lane);
        float a7 = __ldg(g_h + (size_t)s7 * F + lane);
        acc += ((a0 + a1) + (a2 + a3)) + ((a4 + a5) + (a6 + a7));
    }
    for (; i + 2 <= end; i += 2) {
        int s0 = __ldcs(g_ebin + i + 0);
        int s1 = __ldcs(g_ebin + i + 1);
        float a0 = __ldg(g_h + (size_t)s0 * F + lane);
        float a1 = __ldg(g_h + (size_t)s1 * F + lane);
        acc += a0 + a1;
    }
    if (i < end) {
        int s = __ldcs(g_ebin + i);
        acc += __ldg(g_h + (size_t)s * F + lane);
    }

    float r = rsqrtf((float)(cnt + 1));
    float b = __ldg(bias + lane);
    out[(size_t)v * F + lane] = fmaxf(fmaf(acc, r, b), 0.0f);
}

// ---------------------------------------------------------------------------
// Launch
// Inputs (metadata order): feature [N*32 f32], src [E i32], dst [E i32],
//                          W [32*32 f32], bias [32 f32]
// Output: [N*32] f32
// ---------------------------------------------------------------------------
extern "C" void kernel_launch(void* const* d_in, const int* in_sizes, int n_in,
                              void* d_out, int out_size) {
    const float* feature = (const float*)d_in[0];
    const int*   src     = (const int*)d_in[1];
    const int*   dst     = (const int*)d_in[2];
    const float* W       = (const float*)d_in[3];
    const float* bias    = (const float*)d_in[4];
    float*       out     = (float*)d_out;

    int n = in_sizes[0] / F;   // 100000
    int e = in_sizes[1];       // 1600000

    const int B = 256;

    k_hist<<<(e + B - 1) / B, B>>>(dst, e);
    k_allocproject<<<(n + B - 1) / B, B>>>(feature, W, n);
    k_fill<<<(e + B - 1) / B, B>>>(src, dst, e);

    long long athreads = (long long)n * 32;
    int agg_blocks = (int)((athreads + B - 1) / B);
    k_aggregate<<<agg_blocks, B>>>(bias, out, n);
}

// round 9
// speedup vs baseline: 3.6028x; 3.0549x over previous
#include <cuda_runtime.h>
#include <cstdint>

// Problem constants (fixed by the dataset)
#define NN 100000
#define NE 1600000
#define F  32

// Scratch (no cudaMalloc allowed) — referenced directly from device code.
__device__ int           g_cnt[NN];          // in-degree (excl. self-loop)
__device__ int           g_start[NN];        // packed bin start offsets
__device__ unsigned char g_relpos[NE];       // slot within dst bin (max deg << 255)
__device__ int           g_ebin[NE];         // src ids grouped by dst (packed)
__device__ int           g_total;            // global bin allocator
__device__ float         g_h[(size_t)NN * F];// projected features

// ---------------------------------------------------------------------------
// Kernel 1: zero counters
// ---------------------------------------------------------------------------
__global__ void k_zero(int n) {
    int i = blockIdx.x * blockDim.x + threadIdx.x;
    if (i < n) g_cnt[i] = 0;
    if (i == 0) g_total = 0;
}

// ---------------------------------------------------------------------------
// Kernel 2: histogram of dst; keep returned slot (byte) so fill is atomic-free
// ---------------------------------------------------------------------------
__global__ void k_hist(const int* __restrict__ dst, int e) {
    int i = blockIdx.x * blockDim.x + threadIdx.x;
    if (i < e) {
        int d = __ldg(dst + i);
        g_relpos[i] = (unsigned char)atomicAdd(&g_cnt[d], 1);
    }
}

// ---------------------------------------------------------------------------
// Kernel 3 (fused): packed-bin allocation (warp scan + one global atomic per
// warp) + projection h[v] = (x[v] * rsqrt(deg[v])) @ W^T, chunked accumulators.
// ---------------------------------------------------------------------------
__global__ void __launch_bounds__(256) k_allocproject(
        const float* __restrict__ x,
        const float* __restrict__ W, int n) {
    __shared__ float sW[F][F];
    for (int i = threadIdx.x; i < F * F; i += blockDim.x)
        sW[i / F][i % F] = W[i];
    __syncthreads();

    int t = blockIdx.x * blockDim.x + threadIdx.x;
    int lane = t & 31;
    int v = t;

    // ---- bin allocation: inclusive warp scan of counts ----
    int c = (v < n) ? g_cnt[v] : 0;
    int inc = c;
#pragma unroll
    for (int off = 1; off < 32; off <<= 1) {
        int tmp = __shfl_up_sync(0xFFFFFFFFu, inc, off);
        if (lane >= off) inc += tmp;
    }
    int excl = inc - c;
    int base = 0;
    if (lane == 31) base = atomicAdd(&g_total, inc);
    base = __shfl_sync(0xFFFFFFFFu, base, 31);
    if (v < n) g_start[v] = base + excl;

    // ---- projection ----
    if (v >= n) return;

    float s = rsqrtf((float)(c + 1));

    float xr[F];
    const float4* xp = reinterpret_cast<const float4*>(x + (size_t)v * F);
#pragma unroll
    for (int i = 0; i < F / 4; i++) {
        float4 q = __ldg(xp + i);
        xr[4 * i + 0] = q.x * s;
        xr[4 * i + 1] = q.y * s;
        xr[4 * i + 2] = q.z * s;
        xr[4 * i + 3] = q.w * s;
    }

    float4* hp = reinterpret_cast<float4*>(g_h + (size_t)v * F);
#pragma unroll 1
    for (int chunk = 0; chunk < 4; chunk++) {
        float acc[8];
#pragma unroll
        for (int o = 0; o < 8; o++) acc[o] = 0.0f;
#pragma unroll
        for (int i = 0; i < F; i++) {
            float xi = xr[i];
#pragma unroll
            for (int o = 0; o < 8; o++)
                acc[o] = fmaf(xi, sW[chunk * 8 + o][i], acc[o]);
        }
        hp[chunk * 2 + 0] = make_float4(acc[0], acc[1], acc[2], acc[3]);
        hp[chunk * 2 + 1] = make_float4(acc[4], acc[5], acc[6], acc[7]);
    }
}

// ---------------------------------------------------------------------------
// Kernel 4: fill packed bins — pure streaming, slot precomputed by k_hist
// ---------------------------------------------------------------------------
__global__ void k_fill(const int* __restrict__ src,
                       const int* __restrict__ dst, int e) {
    int i = blockIdx.x * blockDim.x + threadIdx.x;
    if (i >= e) return;
    int d = __ldg(dst + i);
    g_ebin[g_start[d] + (int)g_relpos[i]] = __ldg(src + i);
}

// ---------------------------------------------------------------------------
// Kernel 5: warp-per-node gather + fused epilogue. __ldg on EVERYTHING —
// the ebin index loads are on the gather-address critical path and must be
// L1-cacheable (the R8 __ldcs regression proved this: 17us -> 211us).
// ---------------------------------------------------------------------------
__global__ void k_aggregate(const float* __restrict__ bias,
                            float* __restrict__ out, int n) {
    int t = blockIdx.x * blockDim.x + threadIdx.x;
    int v = t >> 5;
    int lane = t & 31;
    if (v >= n) return;

    int start = g_start[v];
    int cnt = g_cnt[v];
    int end = start + cnt;

    float acc = g_h[(size_t)v * F + lane];   // self-loop contribution

    int i = start;
    for (; i + 8 <= end; i += 8) {
        int s0 = __ldg(g_ebin + i + 0);
        int s1 = __ldg(g_ebin + i + 1);
        int s2 = __ldg(g_ebin + i + 2);
        int s3 = __ldg(g_ebin + i + 3);
        int s4 = __ldg(g_ebin + i + 4);
        int s5 = __ldg(g_ebin + i + 5);
        int s6 = __ldg(g_ebin + i + 6);
        int s7 = __ldg(g_ebin + i + 7);
        float a0 = __ldg(g_h + (size_t)s0 * F + lane);
        float a1 = __ldg(g_h + (size_t)s1 * F + lane);
        float a2 = __ldg(g_h + (size_t)s2 * F + lane);
        float a3 = __ldg(g_h + (size_t)s3 * F + lane);
        float a4 = __ldg(g_h + (size_t)s4 * F + lane);
        float a5 = __ldg(g_h + (size_t)s5 * F + lane);
        float a6 = __ldg(g_h + (size_t)s6 * F + lane);
        float a7 = __ldg(g_h + (size_t)s7 * F + lane);
        acc += ((a0 + a1) + (a2 + a3)) + ((a4 + a5) + (a6 + a7));
    }
    for (; i + 2 <= end; i += 2) {
        int s0 = __ldg(g_ebin + i + 0);
        int s1 = __ldg(g_ebin + i + 1);
        float a0 = __ldg(g_h + (size_t)s0 * F + lane);
        float a1 = __ldg(g_h + (size_t)s1 * F + lane);
        acc += a0 + a1;
    }
    if (i < end) {
        int s = __ldg(g_ebin + i);
        acc += __ldg(g_h + (size_t)s * F + lane);
    }

    float r = rsqrtf((float)(cnt + 1));
    float b = __ldg(bias + lane);
    out[(size_t)v * F + lane] = fmaxf(fmaf(acc, r, b), 0.0f);
}

// ---------------------------------------------------------------------------
// Launch
// Inputs (metadata order): feature [N*32 f32], src [E i32], dst [E i32],
//                          W [32*32 f32], bias [32 f32]
// Output: [N*32] f32
// ---------------------------------------------------------------------------
extern "C" void kernel_launch(void* const* d_in, const int* in_sizes, int n_in,
                              void* d_out, int out_size) {
    const float* feature = (const float*)d_in[0];
    const int*   src     = (const int*)d_in[1];
    const int*   dst     = (const int*)d_in[2];
    const float* W       = (const float*)d_in[3];
    const float* bias    = (const float*)d_in[4];
    float*       out     = (float*)d_out;

    int n = in_sizes[0] / F;   // 100000
    int e = in_sizes[1];       // 1600000

    const int B = 256;

    k_zero<<<(n + B - 1) / B, B>>>(n);
    k_hist<<<(e + B - 1) / B, B>>>(dst, e);
    k_allocproject<<<(n + B - 1) / B, B>>>(feature, W, n);
    k_fill<<<(e + B - 1) / B, B>>>(src, dst, e);

    long long athreads = (long long)n * 32;
    int agg_blocks = (int)((athreads + B - 1) / B);
    k_aggregate<<<agg_blocks, B>>>(bias, out, n);
}